// round 15
// baseline (speedup 1.0000x reference)
#include <cuda_runtime.h>
#include <cuda_fp16.h>
#include <math.h>
#include <stdint.h>

#define HIDDEN 1024
#define HEADS 16
#define HEADD 64
#define LAYERS 4
#define MLPD 4096
#define NTOK 1568
#define BATCH 2
#define ROWS (BATCH * NTOK)          // 3136
#define PATCH_K 1536                 // 3*2*16*16
#define MEG (1 << 20)

// ---------------- scratch (device globals; no allocation allowed) ----------------
__device__ float  g_h  [ROWS * HIDDEN];
__device__ __half g_qh  [ROWS * HIDDEN];
__device__ __half g_kh  [ROWS * HIDDEN];
__device__ __half g_vh  [ROWS * HIDDEN];
__device__ __half g_xnh [ROWS * HIDDEN];
__device__ __half g_aoh [ROWS * HIDDEN];
__device__ __half g_mlph[ROWS * MLPD];
__device__ __half g_colh[ROWS * PATCH_K];
__device__ __half g_wrh [12 * MEG];   // per-layer fp16 weights (or patch embed)

// omega_i = 10000^(-i/10), i = 0..9
__constant__ float c_OM[10] = {
    1.0f, 0.3981071705534972f, 0.15848931924611134f, 0.06309573444801933f,
    0.025118864315095794f, 0.01f, 0.003981071705534973f, 0.001584893192461113f,
    0.0006309573444801932f, 0.00025118864315095795f
};

__device__ __forceinline__ uint32_t pack2(float a, float b) {
    __half2 h = __floats2half2_rn(a, b);
    return *(uint32_t*)&h;
}

// ---------------- weight conversion to fp16 ----------------
__global__ void round4_k(const float* __restrict__ in, __half* __restrict__ out, int n4) {
    int i = blockIdx.x * 256 + threadIdx.x;
    if (i >= n4) return;
    float4 v = ((const float4*)in)[i];
    ((uint2*)out)[i] = make_uint2(pack2(v.x, v.y), pack2(v.z, v.w));
}

__global__ void round_layer_k(const float* __restrict__ qw, const float* __restrict__ kw,
                              const float* __restrict__ vw, const float* __restrict__ pw,
                              const float* __restrict__ f1, const float* __restrict__ f2,
                              __half* __restrict__ out) {
    int i = blockIdx.x * 256 + threadIdx.x;      // float4 index, total 3*2^20
    if (i >= 3 * MEG) return;
    int u = i >> 18;
    const float* src;
    int base;
    if (u < 4) {
        src = (u == 0) ? qw : (u == 1) ? kw : (u == 2) ? vw : pw;
        base = i & 262143;
    } else if (u < 8) { src = f1; base = i - 4 * 262144; }
    else             { src = f2; base = i - 8 * 262144; }
    float4 v = ((const float4*)src)[base];
    ((uint2*)out)[i] = make_uint2(pack2(v.x, v.y), pack2(v.z, v.w));
}

// ---------------- im2col (stores fp16) ----------------
__global__ void im2col_k(const float* __restrict__ px, __half* __restrict__ col) {
    int idx = blockIdx.x * 256 + threadIdx.x;
    if (idx >= ROWS * PATCH_K) return;
    int m = idx / PATCH_K;
    int j = idx - m * PATCH_K;
    int c  = j >> 9;
    int r  = j & 511;
    int t  = r >> 8;
    int ph = (r >> 4) & 15;
    int pw = r & 15;
    int b = m / NTOK;
    int n = m - b * NTOK;
    int d  = n / 196;
    int rr = n - d * 196;
    int hy = rr / 14;
    int wx = rr - hy * 14;
    size_t src = ((size_t)((b * 16 + d * 2 + t) * 3 + c)) * (224 * 224)
               + (size_t)(hy * 16 + ph) * 224 + (wx * 16 + pw);
    col[idx] = __float2half_rn(px[src]);
}

// ---------------- fp16 tensor-core GEMM: cp.async 3-stage + ldmatrix ----------------
// TM=4: CTA tile 128x128 (warp tile 64x32). TM=2: CTA tile 64x128 (warp tile 32x32).
__device__ __forceinline__ void mma16(float* c, uint32_t a0, uint32_t a1, uint32_t a2,
                                      uint32_t a3, uint32_t b0, uint32_t b1) {
    asm volatile(
        "mma.sync.aligned.m16n8k16.row.col.f32.f16.f16.f32 "
        "{%0,%1,%2,%3},{%4,%5,%6,%7},{%8,%9},{%0,%1,%2,%3};"
        : "+f"(c[0]), "+f"(c[1]), "+f"(c[2]), "+f"(c[3])
        : "r"(a0), "r"(a1), "r"(a2), "r"(a3), "r"(b0), "r"(b1));
}
__device__ __forceinline__ void cpa16(uint32_t dst, const void* src, int szbytes) {
    asm volatile("cp.async.cg.shared.global [%0], [%1], 16, %2;"
                 :: "r"(dst), "l"(src), "r"(szbytes) : "memory");
}
#define CP_COMMIT() asm volatile("cp.async.commit_group;" ::: "memory")

#define RSU 36                          // u32 row stride (64 halves + pad)
#define BTILE_U32 (128 * RSU)           // 4608 u32 (B tile, always 128 rows)
#define TM4_SMEM (3 * (4 * 32 * RSU + BTILE_U32) * 4)   // 110592
#define TM2_SMEM (3 * (2 * 32 * RSU + BTILE_U32) * 4)   // 82944

template <int MODE, int TM>
__global__ __launch_bounds__(256, 2) void tgemm(
    const __half* __restrict__ A,
    const __half* __restrict__ B0, const __half* __restrict__ B1, const __half* __restrict__ B2,
    const float* __restrict__ bias0, const float* __restrict__ bias1, const float* __restrict__ bias2,
    const float* __restrict__ res, float* __restrict__ C0, float* __restrict__ C1,
    float* __restrict__ C2, int M, int N, int K)
{
    constexpr int ATR = TM * 32;                 // A tile rows
    constexpr int ATILE_U32 = ATR * RSU;
    constexpr int STG_BYTES = (ATILE_U32 + BTILE_U32) * 4;

    extern __shared__ uint32_t smu[];
    uint32_t smbase;
    asm("{ .reg .u64 t; cvta.to.shared.u64 t, %1; cvt.u32.u64 %0, t; }"
        : "=r"(smbase) : "l"(smu));

    int m0 = blockIdx.y * ATR;
    int n0 = blockIdx.x * 128;
    const __half* B = B0;
    const float* bias = bias0;
    float* C = C0;
    int wsel = 0;
    if (MODE == 3) {
        wsel = n0 >> 10;
        if (wsel == 1) { B = B1; bias = bias1; C = C1; }
        else if (wsel == 2) { B = B2; bias = bias2; C = C2; }
        n0 &= 1023;
    }

    const int t = threadIdx.x;
    const int warp = t >> 5, lane = t & 31;
    const int wm = (warp >> 2) * (TM * 16), wn = (warp & 3) * 32;
    const int g = lane >> 2, tig = lane & 3;

    const int asub = lane >> 3;
    const uint32_t a_off =
        (uint32_t)((wm + ((asub & 1) << 3) + (lane & 7)) * (RSU * 4) + (asub >> 1) * 16);
    const int bcol = wn + (lane & 7) + ((lane >> 4) << 3);
    const uint32_t b_off =
        (uint32_t)(bcol * (RSU * 4) + ((lane >> 3) & 1) * 16);

    float acc[TM][4][4];
#pragma unroll
    for (int i = 0; i < TM; i++)
#pragma unroll
        for (int j = 0; j < 4; j++)
#pragma unroll
            for (int q = 0; q < 4; q++) acc[i][j][q] = 0.f;

    const int NC = K >> 6;

    auto stage_cp = [&](int s, int k0) {
        uint32_t sb = smbase + (uint32_t)s * STG_BYTES;
#pragma unroll
        for (int i = 0; i < TM; i++) {
            int e = t + i * 256;                 // ATR*8 slots
            int row = e >> 3, c = e & 7;
            uint32_t off = (uint32_t)((row * RSU + c * 4) * 4);
            int gm = m0 + row;
            const __half* srcA = A + (size_t)(gm < M ? gm : 0) * K + k0 + c * 8;
            cpa16(sb + off, srcA, gm < M ? 16 : 0);
        }
#pragma unroll
        for (int i = 0; i < 4; i++) {
            int e = t + i * 256;
            int row = e >> 3, c = e & 7;
            uint32_t off = (uint32_t)((row * RSU + c * 4) * 4);
            int gn = n0 + row;
            const __half* srcB = B + (size_t)gn * K + k0 + c * 8;
            cpa16(sb + ATILE_U32 * 4 + off, srcB, 16);
        }
    };

    auto compute = [&](int s) {
        uint32_t ab = smbase + (uint32_t)s * STG_BYTES;
        uint32_t bb = ab + ATILE_U32 * 4;
#pragma unroll
        for (int gg = 0; gg < 4; gg++) {
            uint32_t pa[TM][4];
#pragma unroll
            for (int fm = 0; fm < TM; fm++) {
                uint32_t addr = ab + a_off + (uint32_t)(fm * 16 * RSU * 4 + gg * 32);
                asm volatile(
                    "ldmatrix.sync.aligned.m8n8.x4.shared.b16 {%0,%1,%2,%3}, [%4];"
                    : "=r"(pa[fm][0]), "=r"(pa[fm][1]), "=r"(pa[fm][2]), "=r"(pa[fm][3])
                    : "r"(addr));
            }
            uint32_t pb[2][4];
#pragma unroll
            for (int p = 0; p < 2; p++) {
                uint32_t addr = bb + b_off + (uint32_t)(p * 16 * RSU * 4 + gg * 32);
                asm volatile(
                    "ldmatrix.sync.aligned.m8n8.x4.shared.b16 {%0,%1,%2,%3}, [%4];"
                    : "=r"(pb[p][0]), "=r"(pb[p][1]), "=r"(pb[p][2]), "=r"(pb[p][3])
                    : "r"(addr));
            }
#pragma unroll
            for (int fm = 0; fm < TM; fm++)
#pragma unroll
                for (int fn = 0; fn < 4; fn++)
                    mma16(acc[fm][fn], pa[fm][0], pa[fm][1], pa[fm][2], pa[fm][3],
                          pb[fn >> 1][(fn & 1) * 2], pb[fn >> 1][(fn & 1) * 2 + 1]);
        }
    };

    stage_cp(0, 0);
    CP_COMMIT();
    if (NC > 1) { stage_cp(1, 64); CP_COMMIT(); }

    for (int c = 0; c < NC; c++) {
        if (c + 1 < NC) asm volatile("cp.async.wait_group 1;" ::: "memory");
        else            asm volatile("cp.async.wait_group 0;" ::: "memory");
        __syncthreads();
        if (c + 2 < NC) { stage_cp((c + 2) % 3, (c + 2) << 6); CP_COMMIT(); }
        compute(c % 3);
    }

    // epilogue
    __half* Ch = (__half*)C;
#pragma unroll
    for (int fm = 0; fm < TM; fm++) {
        int r0 = m0 + wm + fm * 16 + g;
#pragma unroll
        for (int fn = 0; fn < 4; fn++) {
            int col = n0 + wn + fn * 8 + 2 * tig;
            float b0v = bias[col], b1v = bias[col + 1];
            float om0 = 0.f, om1 = 0.f;
            int axis = 3;
            if (MODE == 3 && wsel < 2) {
                int j = (col & 63) >> 1;
                if (j < 30) {
                    axis = j / 10;
                    int i = j - axis * 10;
                    int i0 = (2 * i) % 10, i1 = (2 * i + 1) % 10;
                    om0 = c_OM[i0]; om1 = c_OM[i1];
                }
            }
#pragma unroll
            for (int hrow = 0; hrow < 2; hrow++) {
                int r = r0 + hrow * 8;
                if (r >= M) continue;
                float v0 = acc[fm][fn][hrow * 2 + 0] + b0v;
                float v1 = acc[fm][fn][hrow * 2 + 1] + b1v;
                if (MODE == 1) {
                    v0 = 0.5f * v0 * (1.f + erff(v0 * 0.70710678118654752f));
                    v1 = 0.5f * v1 * (1.f + erff(v1 * 0.70710678118654752f));
                    *(uint32_t*)&Ch[(size_t)r * N + col] = pack2(v0, v1);
                } else if (MODE == 3) {
                    if (wsel < 2 && axis < 3) {
                        int n = r % NTOK;
                        int dpos = n / 196, rem = n - dpos * 196;
                        int pos = (axis == 0) ? dpos : (axis == 1) ? (rem / 14) : (rem % 14);
                        float fp = (float)pos;
                        float s0, c0, s1, c1;
                        __sincosf(fp * om0, &s0, &c0);
                        __sincosf(fp * om1, &s1, &c1);
                        float nv0 = v0 * c0 - v1 * s0;
                        float nv1 = v1 * c1 + v0 * s1;
                        v0 = nv0; v1 = nv1;
                    }
                    if (wsel == 0) { v0 *= 0.125f; v1 *= 0.125f; }
                    *(uint32_t*)&Ch[(size_t)r * N + col] = pack2(v0, v1);
                } else {
                    if (MODE == 2) {
                        const float* rr = &res[(size_t)r * N + col];
                        v0 += rr[0]; v1 += rr[1];
                    }
                    *(float2*)&C[(size_t)r * N + col] = make_float2(v0, v1);
                }
            }
        }
    }
}

// ---------------- LayerNorm (HALF_OUT: write fp16 for GEMM input) ----------------
template <bool HALF_OUT>
__global__ __launch_bounds__(256) void ln_k(
    const float* __restrict__ x, const float* __restrict__ g,
    const float* __restrict__ b, void* __restrict__ yv)
{
    __shared__ float red[8];
    __shared__ float stat[2];
    int row = blockIdx.x, tid = threadIdx.x;
    const float* xr = x + (size_t)row * HIDDEN;
    float v[4];
    float s = 0.f;
#pragma unroll
    for (int i = 0; i < 4; i++) { v[i] = xr[tid + i * 256]; s += v[i]; }
#pragma unroll
    for (int o = 16; o > 0; o >>= 1) s += __shfl_xor_sync(~0u, s, o);
    if ((tid & 31) == 0) red[tid >> 5] = s;
    __syncthreads();
    if (tid < 32) {
        float t = (tid < 8) ? red[tid] : 0.f;
#pragma unroll
        for (int o = 4; o > 0; o >>= 1) t += __shfl_xor_sync(~0u, t, o);
        if (tid == 0) stat[0] = t * (1.f / HIDDEN);
    }
    __syncthreads();
    float mu = stat[0];
    float s2 = 0.f;
#pragma unroll
    for (int i = 0; i < 4; i++) { float d = v[i] - mu; s2 += d * d; }
#pragma unroll
    for (int o = 16; o > 0; o >>= 1) s2 += __shfl_xor_sync(~0u, s2, o);
    if ((tid & 31) == 0) red[tid >> 5] = s2;
    __syncthreads();
    if (tid < 32) {
        float t = (tid < 8) ? red[tid] : 0.f;
#pragma unroll
        for (int o = 4; o > 0; o >>= 1) t += __shfl_xor_sync(~0u, t, o);
        if (tid == 0) stat[1] = rsqrtf(t * (1.f / HIDDEN) + 1e-6f);
    }
    __syncthreads();
    float rs = stat[1];
#pragma unroll
    for (int i = 0; i < 4; i++) {
        int c = tid + i * 256;
        float o = (v[i] - mu) * rs * g[c] + b[c];
        if (HALF_OUT) ((__half*)yv)[(size_t)row * HIDDEN + c] = __float2half_rn(o);
        else          ((float*)yv)[(size_t)row * HIDDEN + c] = o;
    }
}

// ---------------- Flash attention: Q-tile 64, 128 threads, 3 CTAs/SM ------------
__device__ __forceinline__ void cpa16b(uint32_t dst, const void* src, int szbytes) {
    asm volatile("cp.async.cg.shared.global [%0], [%1], 16, %2;"
                 :: "r"(dst), "l"(src), "r"(szbytes) : "memory");
}
#define AKST 36
#define ASTG_U32 (2 * 64 * AKST)                       // 4608 u32 per stage
#define ATTN_SMEM ((3 * ASTG_U32 + 64 * AKST) * 4)     // 64512 bytes

__global__ __launch_bounds__(128, 3) void attn_h(
    const __half* __restrict__ Q, const __half* __restrict__ K,
    const __half* __restrict__ V, __half* __restrict__ O)
{
    extern __shared__ uint32_t smu[];
    uint32_t smb;
    asm("{ .reg .u64 t; cvta.to.shared.u64 t, %1; cvt.u32.u64 %0, t; }"
        : "=r"(smb) : "l"(smu));

    int b = blockIdx.y >> 4, h = blockIdx.y & 15;
    int q0 = blockIdx.x * 64;
    int tid = threadIdx.x, w = tid >> 5, lane = tid & 31;
    int g = lane >> 2, tq = lane & 3;

    const __half* Qb = Q + (size_t)b * NTOK * HIDDEN + h * HEADD;
    const __half* Kb = K + (size_t)b * NTOK * HIDDEN + h * HEADD;
    const __half* Vb = V + (size_t)b * NTOK * HIDDEN + h * HEADD;

    uint32_t qa[4][4];
    int qrow0 = q0 + w * 16 + g;
    int qrow1 = qrow0 + 8;
    bool qv0 = qrow0 < NTOK, qv1 = qrow1 < NTOK;
    const __half* qp0 = Qb + (size_t)qrow0 * HIDDEN;
    const __half* qp1 = Qb + (size_t)qrow1 * HIDDEN;
#pragma unroll
    for (int ks = 0; ks < 4; ks++) {
        int d0 = ks * 16 + 2 * tq;
        qa[ks][0] = qv0 ? *(const uint32_t*)&qp0[d0] : 0u;
        qa[ks][1] = qv1 ? *(const uint32_t*)&qp1[d0] : 0u;
        qa[ks][2] = qv0 ? *(const uint32_t*)&qp0[d0 + 8] : 0u;
        qa[ks][3] = qv1 ? *(const uint32_t*)&qp1[d0 + 8] : 0u;
    }

    float oacc[8][4];
#pragma unroll
    for (int i = 0; i < 8; i++)
#pragma unroll
        for (int j = 0; j < 4; j++) oacc[i][j] = 0.f;
    float m0 = -1e30f, m1 = -1e30f, l0 = 0.f, l1 = 0.f;

    uint32_t* pw = smu + 3 * ASTG_U32 + w * 16 * AKST;

    int vrow = (lane & 7) + ((lane >> 3) & 1) * 8;
    int vcol = (lane >> 4) * 8;
    uint32_t vaddr_base = (uint32_t)(vrow * AKST * 4 + vcol * 2);

    auto stage_kv = [&](int s, int kt) {
        int k0 = kt * 64;
        uint32_t base = smb + (uint32_t)(s * ASTG_U32 * 4);
#pragma unroll
        for (int i = 0; i < 4; i++) {
            int e = tid + i * 128;
            int r = e >> 3, c = e & 7;
            int ki = k0 + r;
            int ok = (ki < NTOK) ? 16 : 0;
            size_t ro = (size_t)(ki < NTOK ? ki : 0) * HIDDEN + c * 8;
            uint32_t off = (uint32_t)((r * AKST + c * 4) * 4);
            cpa16b(base + off, Kb + ro, ok);
            cpa16b(base + (uint32_t)(64 * AKST * 4) + off, Vb + ro, ok);
        }
    };

    stage_kv(0, 0);
    CP_COMMIT();
    stage_kv(1, 1);
    CP_COMMIT();

    for (int kt = 0; kt < 25; kt++) {
        if (kt < 24) asm volatile("cp.async.wait_group 1;" ::: "memory");
        else         asm volatile("cp.async.wait_group 0;" ::: "memory");
        __syncthreads();
        if (kt + 2 < 25) { stage_kv((kt + 2) % 3, kt + 2); CP_COMMIT(); }

        int s = kt % 3;
        int k0 = kt * 64;
        const uint32_t* Kst = smu + s * ASTG_U32;

        float sacc[8][4];
#pragma unroll
        for (int nf = 0; nf < 8; nf++) {
            sacc[nf][0] = 0.f; sacc[nf][1] = 0.f; sacc[nf][2] = 0.f; sacc[nf][3] = 0.f;
            const uint32_t* krow = &Kst[(nf * 8 + g) * AKST];
#pragma unroll
            for (int ks = 0; ks < 4; ks++) {
                uint32_t b0 = krow[ks * 8 + tq];
                uint32_t b1 = krow[ks * 8 + tq + 4];
                mma16(sacc[nf], qa[ks][0], qa[ks][1], qa[ks][2], qa[ks][3], b0, b1);
            }
        }

        float mx0 = -1e30f, mx1 = -1e30f;
#pragma unroll
        for (int nf = 0; nf < 8; nf++) {
            int col0 = k0 + nf * 8 + 2 * tq;
            if (col0 >= NTOK)     { sacc[nf][0] = -1e30f; sacc[nf][2] = -1e30f; }
            if (col0 + 1 >= NTOK) { sacc[nf][1] = -1e30f; sacc[nf][3] = -1e30f; }
            mx0 = fmaxf(mx0, fmaxf(sacc[nf][0], sacc[nf][1]));
            mx1 = fmaxf(mx1, fmaxf(sacc[nf][2], sacc[nf][3]));
        }
        mx0 = fmaxf(mx0, __shfl_xor_sync(~0u, mx0, 1));
        mx0 = fmaxf(mx0, __shfl_xor_sync(~0u, mx0, 2));
        mx1 = fmaxf(mx1, __shfl_xor_sync(~0u, mx1, 1));
        mx1 = fmaxf(mx1, __shfl_xor_sync(~0u, mx1, 2));
        float mn0 = fmaxf(m0, mx0), mn1 = fmaxf(m1, mx1);
        float corr0 = __expf(m0 - mn0), corr1 = __expf(m1 - mn1);
        m0 = mn0; m1 = mn1;

        float ls0 = 0.f, ls1 = 0.f;
#pragma unroll
        for (int nf = 0; nf < 8; nf++) {
            float p0 = __expf(sacc[nf][0] - mn0);
            float p1 = __expf(sacc[nf][1] - mn0);
            float p2 = __expf(sacc[nf][2] - mn1);
            float p3 = __expf(sacc[nf][3] - mn1);
            ls0 += p0 + p1; ls1 += p2 + p3;
            pw[g * AKST + nf * 4 + tq]       = pack2(p0, p1);
            pw[(g + 8) * AKST + nf * 4 + tq] = pack2(p2, p3);
        }
        ls0 += __shfl_xor_sync(~0u, ls0, 1);
        ls0 += __shfl_xor_sync(~0u, ls0, 2);
        ls1 += __shfl_xor_sync(~0u, ls1, 1);
        ls1 += __shfl_xor_sync(~0u, ls1, 2);
        l0 = l0 * corr0 + ls0;
        l1 = l1 * corr1 + ls1;
#pragma unroll
        for (int nf2 = 0; nf2 < 8; nf2++) {
            oacc[nf2][0] *= corr0; oacc[nf2][1] *= corr0;
            oacc[nf2][2] *= corr1; oacc[nf2][3] *= corr1;
        }
        __syncwarp();

        uint32_t vaddr_t = smb + (uint32_t)(s * ASTG_U32 * 4 + 64 * AKST * 4) + vaddr_base;
#pragma unroll
        for (int ks = 0; ks < 4; ks++) {
            uint32_t a0 = pw[g * AKST + ks * 8 + tq];
            uint32_t a1 = pw[(g + 8) * AKST + ks * 8 + tq];
            uint32_t a2 = pw[g * AKST + ks * 8 + tq + 4];
            uint32_t a3 = pw[(g + 8) * AKST + ks * 8 + tq + 4];
#pragma unroll
            for (int nfp = 0; nfp < 4; nfp++) {
                uint32_t addr = vaddr_t + (uint32_t)(ks * 16 * AKST * 4 + nfp * 32);
                uint32_t v0, v1, v2, v3;
                asm volatile(
                    "ldmatrix.sync.aligned.m8n8.x4.trans.shared.b16 {%0,%1,%2,%3}, [%4];"
                    : "=r"(v0), "=r"(v1), "=r"(v2), "=r"(v3) : "r"(addr));
                mma16(oacc[nfp * 2],     a0, a1, a2, a3, v0, v1);
                mma16(oacc[nfp * 2 + 1], a0, a1, a2, a3, v2, v3);
            }
        }
        __syncwarp();
    }

    float inv0 = 1.f / l0, inv1 = 1.f / l1;
    __half* Ob = O + (size_t)b * NTOK * HIDDEN + h * HEADD;
#pragma unroll
    for (int nf2 = 0; nf2 < 8; nf2++) {
        int d0 = nf2 * 8 + 2 * tq;
        if (qv0)
            *(uint32_t*)&Ob[(size_t)qrow0 * HIDDEN + d0] =
                pack2(oacc[nf2][0] * inv0, oacc[nf2][1] * inv0);
        if (qv1)
            *(uint32_t*)&Ob[(size_t)qrow1 * HIDDEN + d0] =
                pack2(oacc[nf2][2] * inv1, oacc[nf2][3] * inv1);
    }
}

// ---------------- host orchestration ----------------
extern "C" void kernel_launch(void* const* d_in, const int* in_sizes, int n_in,
                              void* d_out, int out_size) {
    (void)in_sizes; (void)n_in; (void)out_size;
    const float* px      = (const float*)d_in[0];
    const float* patch_w = (const float*)d_in[1];
    const float* patch_b = (const float*)d_in[2];
    const float* ln1g = (const float*)d_in[3];
    const float* ln1b = (const float*)d_in[4];
    const float* qw = (const float*)d_in[5];
    const float* qb = (const float*)d_in[6];
    const float* kw = (const float*)d_in[7];
    const float* kb = (const float*)d_in[8];
    const float* vw = (const float*)d_in[9];
    const float* vb = (const float*)d_in[10];
    const float* pw = (const float*)d_in[11];
    const float* pb = (const float*)d_in[12];
    const float* ln2g = (const float*)d_in[13];
    const float* ln2b = (const float*)d_in[14];
    const float* fc1w = (const float*)d_in[15];
    const float* fc1b = (const float*)d_in[16];
    const float* fc2w = (const float*)d_in[17];
    const float* fc2b = (const float*)d_in[18];
    const float* lnfg = (const float*)d_in[19];
    const float* lnfb = (const float*)d_in[20];
    float* out = (float*)d_out;

    void *ph, *pqh, *pkh, *pvh, *pxnh, *paoh, *pmlph, *pcolh, *pwrh;
    cudaGetSymbolAddress(&ph,  g_h);
    cudaGetSymbolAddress(&pqh, g_qh);
    cudaGetSymbolAddress(&pkh, g_kh);
    cudaGetSymbolAddress(&pvh, g_vh);
    cudaGetSymbolAddress(&pxnh, g_xnh);
    cudaGetSymbolAddress(&paoh, g_aoh);
    cudaGetSymbolAddress(&pmlph, g_mlph);
    cudaGetSymbolAddress(&pcolh, g_colh);
    cudaGetSymbolAddress(&pwrh, g_wrh);
    float*  h    = (float*)ph;
    __half* qh   = (__half*)pqh;
    __half* kh   = (__half*)pkh;
    __half* vh   = (__half*)pvh;
    __half* xnh  = (__half*)pxnh;
    __half* aoh  = (__half*)paoh;
    __half* mlph = (__half*)pmlph;
    __half* colh = (__half*)pcolh;
    __half* wrh  = (__half*)pwrh;

    cudaFuncSetAttribute(tgemm<0,2>, cudaFuncAttributeMaxDynamicSharedMemorySize, TM2_SMEM);
    cudaFuncSetAttribute(tgemm<3,2>, cudaFuncAttributeMaxDynamicSharedMemorySize, TM2_SMEM);
    cudaFuncSetAttribute(tgemm<2,2>, cudaFuncAttributeMaxDynamicSharedMemorySize, TM2_SMEM);
    cudaFuncSetAttribute(tgemm<1,4>, cudaFuncAttributeMaxDynamicSharedMemorySize, TM4_SMEM);
    cudaFuncSetAttribute(attn_h, cudaFuncAttributeMaxDynamicSharedMemorySize, ATTN_SMEM);

    // patch embed: M tiles of 64 -> 49
    im2col_k<<<(ROWS * PATCH_K + 255) / 256, 256>>>(px, colh);
    round4_k<<<(HIDDEN * PATCH_K / 4 + 255) / 256, 256>>>(patch_w, wrh, HIDDEN * PATCH_K / 4);
    tgemm<0,2><<<dim3(8, 49), 256, TM2_SMEM>>>(
        colh, wrh, wrh, wrh, patch_b, patch_b, patch_b,
        nullptr, h, h, h, ROWS, HIDDEN, PATCH_K);

    for (int l = 0; l < LAYERS; l++) {
        size_t wo = (size_t)l * HIDDEN * HIDDEN;
        size_t bo = (size_t)l * HIDDEN;
        round_layer_k<<<(3 * MEG + 255) / 256, 256>>>(
            qw + wo, kw + wo, vw + wo, pw + wo,
            fc1w + (size_t)l * MLPD * HIDDEN, fc2w + (size_t)l * HIDDEN * MLPD, wrh);
        // attention block (RoPE fused into QKV epilogue)
        ln_k<true><<<ROWS, 256>>>(h, ln1g + bo, ln1b + bo, xnh);
        tgemm<3,2><<<dim3(24, 49), 256, TM2_SMEM>>>(
            xnh, wrh, wrh + MEG, wrh + 2 * MEG, qb + bo, kb + bo, vb + bo,
            nullptr, (float*)qh, (float*)kh, (float*)vh, ROWS, HIDDEN, HIDDEN);
        attn_h<<<dim3(25, BATCH * HEADS), 128, ATTN_SMEM>>>(qh, kh, vh, aoh);
        tgemm<2,2><<<dim3(8, 49), 256, TM2_SMEM>>>(
            aoh, wrh + 3 * MEG, wrh, wrh, pb + bo, pb + bo, pb + bo,
            h, h, h, h, ROWS, HIDDEN, HIDDEN);
        // MLP block
        ln_k<true><<<ROWS, 256>>>(h, ln2g + bo, ln2b + bo, xnh);
        tgemm<1,4><<<dim3(MLPD / 128, 25), 256, TM4_SMEM>>>(
            xnh, wrh + 4 * MEG, wrh, wrh, fc1b + (size_t)l * MLPD, fc1b, fc1b,
            nullptr, (float*)mlph, (float*)mlph, (float*)mlph, ROWS, MLPD, HIDDEN);
        tgemm<2,2><<<dim3(8, 49), 256, TM2_SMEM>>>(
            mlph, wrh + 8 * MEG, wrh, wrh, fc2b + bo, fc2b, fc2b,
            h, h, h, h, ROWS, HIDDEN, MLPD);
    }

    ln_k<false><<<ROWS, 256>>>(h, lnfg, lnfb, out);
}

// round 16
// speedup vs baseline: 1.0133x; 1.0133x over previous
#include <cuda_runtime.h>
#include <cuda_fp16.h>
#include <math.h>
#include <stdint.h>

#define HIDDEN 1024
#define HEADS 16
#define HEADD 64
#define LAYERS 4
#define MLPD 4096
#define NTOK 1568
#define BATCH 2
#define ROWS (BATCH * NTOK)          // 3136
#define PATCH_K 1536                 // 3*2*16*16
#define MEG (1 << 20)

// ---------------- scratch (device globals; no allocation allowed) ----------------
__device__ float  g_h  [ROWS * HIDDEN];
__device__ __half g_qh  [ROWS * HIDDEN];
__device__ __half g_kh  [ROWS * HIDDEN];
__device__ __half g_vh  [ROWS * HIDDEN];
__device__ __half g_xnh [ROWS * HIDDEN];
__device__ __half g_aoh [ROWS * HIDDEN];
__device__ __half g_mlph[ROWS * MLPD];
__device__ __half g_colh[ROWS * PATCH_K];
__device__ __half g_wrh [12 * MEG];   // per-layer fp16 weights (or patch embed)

// omega_i = 10000^(-i/10), i = 0..9
__constant__ float c_OM[10] = {
    1.0f, 0.3981071705534972f, 0.15848931924611134f, 0.06309573444801933f,
    0.025118864315095794f, 0.01f, 0.003981071705534973f, 0.001584893192461113f,
    0.0006309573444801932f, 0.00025118864315095795f
};

__device__ __forceinline__ uint32_t pack2(float a, float b) {
    __half2 h = __floats2half2_rn(a, b);
    return *(uint32_t*)&h;
}

// ---------------- weight conversion to fp16 ----------------
__global__ void round4_k(const float* __restrict__ in, __half* __restrict__ out, int n4) {
    int i = blockIdx.x * 256 + threadIdx.x;
    if (i >= n4) return;
    float4 v = ((const float4*)in)[i];
    ((uint2*)out)[i] = make_uint2(pack2(v.x, v.y), pack2(v.z, v.w));
}

__global__ void round_layer_k(const float* __restrict__ qw, const float* __restrict__ kw,
                              const float* __restrict__ vw, const float* __restrict__ pw,
                              const float* __restrict__ f1, const float* __restrict__ f2,
                              __half* __restrict__ out) {
    int i = blockIdx.x * 256 + threadIdx.x;      // float4 index, total 3*2^20
    if (i >= 3 * MEG) return;
    int u = i >> 18;
    const float* src;
    int base;
    if (u < 4) {
        src = (u == 0) ? qw : (u == 1) ? kw : (u == 2) ? vw : pw;
        base = i & 262143;
    } else if (u < 8) { src = f1; base = i - 4 * 262144; }
    else             { src = f2; base = i - 8 * 262144; }
    float4 v = ((const float4*)src)[base];
    ((uint2*)out)[i] = make_uint2(pack2(v.x, v.y), pack2(v.z, v.w));
}

// ---------------- im2col (stores fp16) ----------------
__global__ void im2col_k(const float* __restrict__ px, __half* __restrict__ col) {
    int idx = blockIdx.x * 256 + threadIdx.x;
    if (idx >= ROWS * PATCH_K) return;
    int m = idx / PATCH_K;
    int j = idx - m * PATCH_K;
    int c  = j >> 9;
    int r  = j & 511;
    int t  = r >> 8;
    int ph = (r >> 4) & 15;
    int pw = r & 15;
    int b = m / NTOK;
    int n = m - b * NTOK;
    int d  = n / 196;
    int rr = n - d * 196;
    int hy = rr / 14;
    int wx = rr - hy * 14;
    size_t src = ((size_t)((b * 16 + d * 2 + t) * 3 + c)) * (224 * 224)
               + (size_t)(hy * 16 + ph) * 224 + (wx * 16 + pw);
    col[idx] = __float2half_rn(px[src]);
}

// ---------------- fp16 tensor-core GEMM: cp.async 3-stage + ldmatrix ----------------
__device__ __forceinline__ void mma16(float* c, uint32_t a0, uint32_t a1, uint32_t a2,
                                      uint32_t a3, uint32_t b0, uint32_t b1) {
    asm volatile(
        "mma.sync.aligned.m16n8k16.row.col.f32.f16.f16.f32 "
        "{%0,%1,%2,%3},{%4,%5,%6,%7},{%8,%9},{%0,%1,%2,%3};"
        : "+f"(c[0]), "+f"(c[1]), "+f"(c[2]), "+f"(c[3])
        : "r"(a0), "r"(a1), "r"(a2), "r"(a3), "r"(b0), "r"(b1));
}
__device__ __forceinline__ void cpa16(uint32_t dst, const void* src, int szbytes) {
    asm volatile("cp.async.cg.shared.global [%0], [%1], 16, %2;"
                 :: "r"(dst), "l"(src), "r"(szbytes) : "memory");
}
#define CP_COMMIT() asm volatile("cp.async.commit_group;" ::: "memory")

#define RSU 36                         // u32 row stride
#define TILE_U32 (128 * RSU)           // 4608 u32 per operand tile
#define STAGE_BYTES (2 * TILE_U32 * 4) // 36864
#define GEMM_SMEM (3 * STAGE_BYTES)    // 110592

template <int MODE>
__global__ __launch_bounds__(256, 2) void tgemm(
    const __half* __restrict__ A,
    const __half* __restrict__ B0, const __half* __restrict__ B1, const __half* __restrict__ B2,
    const float* __restrict__ bias0, const float* __restrict__ bias1, const float* __restrict__ bias2,
    const float* __restrict__ res, float* __restrict__ C0, float* __restrict__ C1,
    float* __restrict__ C2, int M, int N, int K)
{
    extern __shared__ uint32_t smu[];
    uint32_t smbase;
    asm("{ .reg .u64 t; cvta.to.shared.u64 t, %1; cvt.u32.u64 %0, t; }"
        : "=r"(smbase) : "l"(smu));

    int m0 = blockIdx.y * 128;
    int n0 = blockIdx.x * 128;
    const __half* B = B0;
    const float* bias = bias0;
    float* C = C0;
    int wsel = 0;
    if (MODE == 3) {
        wsel = n0 >> 10;
        if (wsel == 1) { B = B1; bias = bias1; C = C1; }
        else if (wsel == 2) { B = B2; bias = bias2; C = C2; }
        n0 &= 1023;
    }

    const int t = threadIdx.x;
    const int warp = t >> 5, lane = t & 31;
    const int wm = (warp >> 2) * 64, wn = (warp & 3) * 32;
    const int g = lane >> 2, tig = lane & 3;

    const int asub = lane >> 3;
    const uint32_t a_off =
        (uint32_t)((wm + ((asub & 1) << 3) + (lane & 7)) * (RSU * 4) + (asub >> 1) * 16);
    const int bcol = wn + (lane & 7) + ((lane >> 4) << 3);
    const uint32_t b_off =
        (uint32_t)(bcol * (RSU * 4) + ((lane >> 3) & 1) * 16);

    float acc[4][4][4];
#pragma unroll
    for (int i = 0; i < 4; i++)
#pragma unroll
        for (int j = 0; j < 4; j++)
#pragma unroll
            for (int q = 0; q < 4; q++) acc[i][j][q] = 0.f;

    const int NC = K >> 6;

    auto stage_cp = [&](int s, int k0) {
        uint32_t sb = smbase + (uint32_t)s * STAGE_BYTES;
#pragma unroll
        for (int i = 0; i < 4; i++) {
            int e = t + i * 256;
            int row = e >> 3, c = e & 7;
            uint32_t off = (uint32_t)((row * RSU + c * 4) * 4);
            int gm = m0 + row;
            const __half* srcA = A + (size_t)(gm < M ? gm : 0) * K + k0 + c * 8;
            cpa16(sb + off, srcA, gm < M ? 16 : 0);
            int gn = n0 + row;
            const __half* srcB = B + (size_t)gn * K + k0 + c * 8;
            cpa16(sb + TILE_U32 * 4 + off, srcB, 16);
        }
    };

    auto compute = [&](int s) {
        uint32_t ab = smbase + (uint32_t)s * STAGE_BYTES;
        uint32_t bb = ab + TILE_U32 * 4;
#pragma unroll
        for (int gg = 0; gg < 4; gg++) {
            uint32_t pa[4][4];
#pragma unroll
            for (int fm = 0; fm < 4; fm++) {
                uint32_t addr = ab + a_off + (uint32_t)(fm * 16 * RSU * 4 + gg * 32);
                asm volatile(
                    "ldmatrix.sync.aligned.m8n8.x4.shared.b16 {%0,%1,%2,%3}, [%4];"
                    : "=r"(pa[fm][0]), "=r"(pa[fm][1]), "=r"(pa[fm][2]), "=r"(pa[fm][3])
                    : "r"(addr));
            }
            uint32_t pb[2][4];
#pragma unroll
            for (int p = 0; p < 2; p++) {
                uint32_t addr = bb + b_off + (uint32_t)(p * 16 * RSU * 4 + gg * 32);
                asm volatile(
                    "ldmatrix.sync.aligned.m8n8.x4.shared.b16 {%0,%1,%2,%3}, [%4];"
                    : "=r"(pb[p][0]), "=r"(pb[p][1]), "=r"(pb[p][2]), "=r"(pb[p][3])
                    : "r"(addr));
            }
#pragma unroll
            for (int fm = 0; fm < 4; fm++)
#pragma unroll
                for (int fn = 0; fn < 4; fn++)
                    mma16(acc[fm][fn], pa[fm][0], pa[fm][1], pa[fm][2], pa[fm][3],
                          pb[fn >> 1][(fn & 1) * 2], pb[fn >> 1][(fn & 1) * 2 + 1]);
        }
    };

    stage_cp(0, 0);
    CP_COMMIT();
    if (NC > 1) { stage_cp(1, 64); CP_COMMIT(); }

    for (int c = 0; c < NC; c++) {
        if (c + 1 < NC) asm volatile("cp.async.wait_group 1;" ::: "memory");
        else            asm volatile("cp.async.wait_group 0;" ::: "memory");
        __syncthreads();
        if (c + 2 < NC) { stage_cp((c + 2) % 3, (c + 2) << 6); CP_COMMIT(); }
        compute(c % 3);
    }

    // epilogue
    __half* Ch = (__half*)C;
#pragma unroll
    for (int fm = 0; fm < 4; fm++) {
        int r0 = m0 + wm + fm * 16 + g;
#pragma unroll
        for (int fn = 0; fn < 4; fn++) {
            int col = n0 + wn + fn * 8 + 2 * tig;
            float b0v = bias[col], b1v = bias[col + 1];
            float om0 = 0.f, om1 = 0.f;
            int axis = 3;
            if (MODE == 3 && wsel < 2) {
                int j = (col & 63) >> 1;
                if (j < 30) {
                    axis = j / 10;
                    int i = j - axis * 10;
                    int i0 = (2 * i) % 10, i1 = (2 * i + 1) % 10;
                    om0 = c_OM[i0]; om1 = c_OM[i1];
                }
            }
#pragma unroll
            for (int hrow = 0; hrow < 2; hrow++) {
                int r = r0 + hrow * 8;
                if (r >= M) continue;
                float v0 = acc[fm][fn][hrow * 2 + 0] + b0v;
                float v1 = acc[fm][fn][hrow * 2 + 1] + b1v;
                if (MODE == 1) {
                    v0 = 0.5f * v0 * (1.f + erff(v0 * 0.70710678118654752f));
                    v1 = 0.5f * v1 * (1.f + erff(v1 * 0.70710678118654752f));
                    *(uint32_t*)&Ch[(size_t)r * N + col] = pack2(v0, v1);
                } else if (MODE == 3) {
                    if (wsel < 2 && axis < 3) {
                        int n = r % NTOK;
                        int dpos = n / 196, rem = n - dpos * 196;
                        int pos = (axis == 0) ? dpos : (axis == 1) ? (rem / 14) : (rem % 14);
                        float fp = (float)pos;
                        float s0, c0, s1, c1;
                        __sincosf(fp * om0, &s0, &c0);
                        __sincosf(fp * om1, &s1, &c1);
                        float nv0 = v0 * c0 - v1 * s0;
                        float nv1 = v1 * c1 + v0 * s1;
                        v0 = nv0; v1 = nv1;
                    }
                    if (wsel == 0) { v0 *= 0.125f; v1 *= 0.125f; }
                    *(uint32_t*)&Ch[(size_t)r * N + col] = pack2(v0, v1);
                } else {
                    if (MODE == 2) {
                        const float* rr = &res[(size_t)r * N + col];
                        v0 += rr[0]; v1 += rr[1];
                    }
                    *(float2*)&C[(size_t)r * N + col] = make_float2(v0, v1);
                }
            }
        }
    }
}

// ---------------- LayerNorm: warp-per-row, no barriers ----------------
template <bool HALF_OUT>
__global__ __launch_bounds__(256) void ln_w(
    const float* __restrict__ x, const float* __restrict__ g,
    const float* __restrict__ b, void* __restrict__ yv)
{
    int warp = threadIdx.x >> 5, lane = threadIdx.x & 31;
    int row = blockIdx.x * 8 + warp;
    const float* xr = x + (size_t)row * HIDDEN;

    float4 v[8];
    float s = 0.f;
#pragma unroll
    for (int i = 0; i < 8; i++) {
        v[i] = ((const float4*)xr)[i * 32 + lane];
        s += (v[i].x + v[i].y) + (v[i].z + v[i].w);
    }
#pragma unroll
    for (int o = 16; o > 0; o >>= 1) s += __shfl_xor_sync(~0u, s, o);
    float mu = s * (1.f / HIDDEN);

    float s2 = 0.f;
#pragma unroll
    for (int i = 0; i < 8; i++) {
        float d0 = v[i].x - mu, d1 = v[i].y - mu, d2 = v[i].z - mu, d3 = v[i].w - mu;
        s2 += (d0 * d0 + d1 * d1) + (d2 * d2 + d3 * d3);
    }
#pragma unroll
    for (int o = 16; o > 0; o >>= 1) s2 += __shfl_xor_sync(~0u, s2, o);
    float rs = rsqrtf(s2 * (1.f / HIDDEN) + 1e-6f);

#pragma unroll
    for (int i = 0; i < 8; i++) {
        int c = (i * 32 + lane) * 4;
        float4 gv = *(const float4*)&g[c];
        float4 bv = *(const float4*)&b[c];
        float o0 = (v[i].x - mu) * rs * gv.x + bv.x;
        float o1 = (v[i].y - mu) * rs * gv.y + bv.y;
        float o2 = (v[i].z - mu) * rs * gv.z + bv.z;
        float o3 = (v[i].w - mu) * rs * gv.w + bv.w;
        if (HALF_OUT) {
            *(uint2*)&((__half*)yv)[(size_t)row * HIDDEN + c] =
                make_uint2(pack2(o0, o1), pack2(o2, o3));
        } else {
            *(float4*)&((float*)yv)[(size_t)row * HIDDEN + c] =
                make_float4(o0, o1, o2, o3);
        }
    }
}

// ---------------- Flash attention: Q-tile 128, cp.async 3-stage K/V pipeline ------
#define AKST 36
#define ASTG_U32 (2 * 64 * AKST)
#define ATTN_SMEM ((3 * ASTG_U32 + 128 * AKST) * 4)   // 73728 bytes

__global__ __launch_bounds__(256, 2) void attn_h(
    const __half* __restrict__ Q, const __half* __restrict__ K,
    const __half* __restrict__ V, __half* __restrict__ O)
{
    extern __shared__ uint32_t smu[];
    uint32_t smb;
    asm("{ .reg .u64 t; cvta.to.shared.u64 t, %1; cvt.u32.u64 %0, t; }"
        : "=r"(smb) : "l"(smu));

    int b = blockIdx.y >> 4, h = blockIdx.y & 15;
    int q0 = blockIdx.x * 128;
    int tid = threadIdx.x, w = tid >> 5, lane = tid & 31;
    int g = lane >> 2, tq = lane & 3;

    const __half* Qb = Q + (size_t)b * NTOK * HIDDEN + h * HEADD;
    const __half* Kb = K + (size_t)b * NTOK * HIDDEN + h * HEADD;
    const __half* Vb = V + (size_t)b * NTOK * HIDDEN + h * HEADD;

    uint32_t qa[4][4];
    int qrow0 = q0 + w * 16 + g;
    int qrow1 = qrow0 + 8;
    bool qv0 = qrow0 < NTOK, qv1 = qrow1 < NTOK;
    const __half* qp0 = Qb + (size_t)qrow0 * HIDDEN;
    const __half* qp1 = Qb + (size_t)qrow1 * HIDDEN;
#pragma unroll
    for (int ks = 0; ks < 4; ks++) {
        int d0 = ks * 16 + 2 * tq;
        qa[ks][0] = qv0 ? *(const uint32_t*)&qp0[d0] : 0u;
        qa[ks][1] = qv1 ? *(const uint32_t*)&qp1[d0] : 0u;
        qa[ks][2] = qv0 ? *(const uint32_t*)&qp0[d0 + 8] : 0u;
        qa[ks][3] = qv1 ? *(const uint32_t*)&qp1[d0 + 8] : 0u;
    }

    float oacc[8][4];
#pragma unroll
    for (int i = 0; i < 8; i++)
#pragma unroll
        for (int j = 0; j < 4; j++) oacc[i][j] = 0.f;
    float m0 = -1e30f, m1 = -1e30f, l0 = 0.f, l1 = 0.f;

    uint32_t* pw = smu + 3 * ASTG_U32 + w * 16 * AKST;

    int vrow = (lane & 7) + ((lane >> 3) & 1) * 8;
    int vcol = (lane >> 4) * 8;
    uint32_t vaddr_base = (uint32_t)(vrow * AKST * 4 + vcol * 2);

    auto stage_kv = [&](int s, int kt) {
        int k0 = kt * 64;
        uint32_t base = smb + (uint32_t)(s * ASTG_U32 * 4);
#pragma unroll
        for (int i = 0; i < 2; i++) {
            int e = tid + i * 256;
            int r = e >> 3, c = e & 7;
            int ki = k0 + r;
            int ok = (ki < NTOK) ? 16 : 0;
            size_t ro = (size_t)(ki < NTOK ? ki : 0) * HIDDEN + c * 8;
            uint32_t off = (uint32_t)((r * AKST + c * 4) * 4);
            cpa16(base + off, Kb + ro, ok);
            cpa16(base + (uint32_t)(64 * AKST * 4) + off, Vb + ro, ok);
        }
    };

    stage_kv(0, 0);
    CP_COMMIT();
    stage_kv(1, 1);
    CP_COMMIT();

    for (int kt = 0; kt < 25; kt++) {
        if (kt < 24) asm volatile("cp.async.wait_group 1;" ::: "memory");
        else         asm volatile("cp.async.wait_group 0;" ::: "memory");
        __syncthreads();
        if (kt + 2 < 25) { stage_kv((kt + 2) % 3, kt + 2); CP_COMMIT(); }

        int s = kt % 3;
        int k0 = kt * 64;
        const uint32_t* Kst = smu + s * ASTG_U32;

        float sacc[8][4];
#pragma unroll
        for (int nf = 0; nf < 8; nf++) {
            sacc[nf][0] = 0.f; sacc[nf][1] = 0.f; sacc[nf][2] = 0.f; sacc[nf][3] = 0.f;
            const uint32_t* krow = &Kst[(nf * 8 + g) * AKST];
#pragma unroll
            for (int ks = 0; ks < 4; ks++) {
                uint32_t b0 = krow[ks * 8 + tq];
                uint32_t b1 = krow[ks * 8 + tq + 4];
                mma16(sacc[nf], qa[ks][0], qa[ks][1], qa[ks][2], qa[ks][3], b0, b1);
            }
        }

        float mx0 = -1e30f, mx1 = -1e30f;
#pragma unroll
        for (int nf = 0; nf < 8; nf++) {
            int col0 = k0 + nf * 8 + 2 * tq;
            if (col0 >= NTOK)     { sacc[nf][0] = -1e30f; sacc[nf][2] = -1e30f; }
            if (col0 + 1 >= NTOK) { sacc[nf][1] = -1e30f; sacc[nf][3] = -1e30f; }
            mx0 = fmaxf(mx0, fmaxf(sacc[nf][0], sacc[nf][1]));
            mx1 = fmaxf(mx1, fmaxf(sacc[nf][2], sacc[nf][3]));
        }
        mx0 = fmaxf(mx0, __shfl_xor_sync(~0u, mx0, 1));
        mx0 = fmaxf(mx0, __shfl_xor_sync(~0u, mx0, 2));
        mx1 = fmaxf(mx1, __shfl_xor_sync(~0u, mx1, 1));
        mx1 = fmaxf(mx1, __shfl_xor_sync(~0u, mx1, 2));
        float mn0 = fmaxf(m0, mx0), mn1 = fmaxf(m1, mx1);
        float corr0 = __expf(m0 - mn0), corr1 = __expf(m1 - mn1);
        m0 = mn0; m1 = mn1;

        float ls0 = 0.f, ls1 = 0.f;
#pragma unroll
        for (int nf = 0; nf < 8; nf++) {
            float p0 = __expf(sacc[nf][0] - mn0);
            float p1 = __expf(sacc[nf][1] - mn0);
            float p2 = __expf(sacc[nf][2] - mn1);
            float p3 = __expf(sacc[nf][3] - mn1);
            ls0 += p0 + p1; ls1 += p2 + p3;
            pw[g * AKST + nf * 4 + tq]       = pack2(p0, p1);
            pw[(g + 8) * AKST + nf * 4 + tq] = pack2(p2, p3);
        }
        ls0 += __shfl_xor_sync(~0u, ls0, 1);
        ls0 += __shfl_xor_sync(~0u, ls0, 2);
        ls1 += __shfl_xor_sync(~0u, ls1, 1);
        ls1 += __shfl_xor_sync(~0u, ls1, 2);
        l0 = l0 * corr0 + ls0;
        l1 = l1 * corr1 + ls1;
#pragma unroll
        for (int nf2 = 0; nf2 < 8; nf2++) {
            oacc[nf2][0] *= corr0; oacc[nf2][1] *= corr0;
            oacc[nf2][2] *= corr1; oacc[nf2][3] *= corr1;
        }
        __syncwarp();

        uint32_t vaddr_t = smb + (uint32_t)(s * ASTG_U32 * 4 + 64 * AKST * 4) + vaddr_base;
#pragma unroll
        for (int ks = 0; ks < 4; ks++) {
            uint32_t a0 = pw[g * AKST + ks * 8 + tq];
            uint32_t a1 = pw[(g + 8) * AKST + ks * 8 + tq];
            uint32_t a2 = pw[g * AKST + ks * 8 + tq + 4];
            uint32_t a3 = pw[(g + 8) * AKST + ks * 8 + tq + 4];
#pragma unroll
            for (int nfp = 0; nfp < 4; nfp++) {
                uint32_t addr = vaddr_t + (uint32_t)(ks * 16 * AKST * 4 + nfp * 32);
                uint32_t v0, v1, v2, v3;
                asm volatile(
                    "ldmatrix.sync.aligned.m8n8.x4.trans.shared.b16 {%0,%1,%2,%3}, [%4];"
                    : "=r"(v0), "=r"(v1), "=r"(v2), "=r"(v3) : "r"(addr));
                mma16(oacc[nfp * 2],     a0, a1, a2, a3, v0, v1);
                mma16(oacc[nfp * 2 + 1], a0, a1, a2, a3, v2, v3);
            }
        }
        __syncwarp();
    }

    float inv0 = 1.f / l0, inv1 = 1.f / l1;
    __half* Ob = O + (size_t)b * NTOK * HIDDEN + h * HEADD;
#pragma unroll
    for (int nf2 = 0; nf2 < 8; nf2++) {
        int d0 = nf2 * 8 + 2 * tq;
        if (qv0)
            *(uint32_t*)&Ob[(size_t)qrow0 * HIDDEN + d0] =
                pack2(oacc[nf2][0] * inv0, oacc[nf2][1] * inv0);
        if (qv1)
            *(uint32_t*)&Ob[(size_t)qrow1 * HIDDEN + d0] =
                pack2(oacc[nf2][2] * inv1, oacc[nf2][3] * inv1);
    }
}

// ---------------- host orchestration ----------------
extern "C" void kernel_launch(void* const* d_in, const int* in_sizes, int n_in,
                              void* d_out, int out_size) {
    (void)in_sizes; (void)n_in; (void)out_size;
    const float* px      = (const float*)d_in[0];
    const float* patch_w = (const float*)d_in[1];
    const float* patch_b = (const float*)d_in[2];
    const float* ln1g = (const float*)d_in[3];
    const float* ln1b = (const float*)d_in[4];
    const float* qw = (const float*)d_in[5];
    const float* qb = (const float*)d_in[6];
    const float* kw = (const float*)d_in[7];
    const float* kb = (const float*)d_in[8];
    const float* vw = (const float*)d_in[9];
    const float* vb = (const float*)d_in[10];
    const float* pw = (const float*)d_in[11];
    const float* pb = (const float*)d_in[12];
    const float* ln2g = (const float*)d_in[13];
    const float* ln2b = (const float*)d_in[14];
    const float* fc1w = (const float*)d_in[15];
    const float* fc1b = (const float*)d_in[16];
    const float* fc2w = (const float*)d_in[17];
    const float* fc2b = (const float*)d_in[18];
    const float* lnfg = (const float*)d_in[19];
    const float* lnfb = (const float*)d_in[20];
    float* out = (float*)d_out;

    void *ph, *pqh, *pkh, *pvh, *pxnh, *paoh, *pmlph, *pcolh, *pwrh;
    cudaGetSymbolAddress(&ph,  g_h);
    cudaGetSymbolAddress(&pqh, g_qh);
    cudaGetSymbolAddress(&pkh, g_kh);
    cudaGetSymbolAddress(&pvh, g_vh);
    cudaGetSymbolAddress(&pxnh, g_xnh);
    cudaGetSymbolAddress(&paoh, g_aoh);
    cudaGetSymbolAddress(&pmlph, g_mlph);
    cudaGetSymbolAddress(&pcolh, g_colh);
    cudaGetSymbolAddress(&pwrh, g_wrh);
    float*  h    = (float*)ph;
    __half* qh   = (__half*)pqh;
    __half* kh   = (__half*)pkh;
    __half* vh   = (__half*)pvh;
    __half* xnh  = (__half*)pxnh;
    __half* aoh  = (__half*)paoh;
    __half* mlph = (__half*)pmlph;
    __half* colh = (__half*)pcolh;
    __half* wrh  = (__half*)pwrh;

    cudaFuncSetAttribute(tgemm<0>, cudaFuncAttributeMaxDynamicSharedMemorySize, GEMM_SMEM);
    cudaFuncSetAttribute(tgemm<1>, cudaFuncAttributeMaxDynamicSharedMemorySize, GEMM_SMEM);
    cudaFuncSetAttribute(tgemm<2>, cudaFuncAttributeMaxDynamicSharedMemorySize, GEMM_SMEM);
    cudaFuncSetAttribute(tgemm<3>, cudaFuncAttributeMaxDynamicSharedMemorySize, GEMM_SMEM);
    cudaFuncSetAttribute(attn_h, cudaFuncAttributeMaxDynamicSharedMemorySize, ATTN_SMEM);

    // patch embed
    im2col_k<<<(ROWS * PATCH_K + 255) / 256, 256>>>(px, colh);
    round4_k<<<(HIDDEN * PATCH_K / 4 + 255) / 256, 256>>>(patch_w, wrh, HIDDEN * PATCH_K / 4);
    tgemm<0><<<dim3(8, 25), 256, GEMM_SMEM>>>(
        colh, wrh, wrh, wrh, patch_b, patch_b, patch_b,
        nullptr, h, h, h, ROWS, HIDDEN, PATCH_K);

    for (int l = 0; l < LAYERS; l++) {
        size_t wo = (size_t)l * HIDDEN * HIDDEN;
        size_t bo = (size_t)l * HIDDEN;
        round_layer_k<<<(3 * MEG + 255) / 256, 256>>>(
            qw + wo, kw + wo, vw + wo, pw + wo,
            fc1w + (size_t)l * MLPD * HIDDEN, fc2w + (size_t)l * HIDDEN * MLPD, wrh);
        // attention block (RoPE fused into QKV epilogue)
        ln_w<true><<<ROWS / 8, 256>>>(h, ln1g + bo, ln1b + bo, xnh);
        tgemm<3><<<dim3(24, 25), 256, GEMM_SMEM>>>(
            xnh, wrh, wrh + MEG, wrh + 2 * MEG, qb + bo, kb + bo, vb + bo,
            nullptr, (float*)qh, (float*)kh, (float*)vh, ROWS, HIDDEN, HIDDEN);
        attn_h<<<dim3(13, BATCH * HEADS), 256, ATTN_SMEM>>>(qh, kh, vh, aoh);
        tgemm<2><<<dim3(8, 25), 256, GEMM_SMEM>>>(
            aoh, wrh + 3 * MEG, wrh, wrh, pb + bo, pb + bo, pb + bo,
            h, h, h, h, ROWS, HIDDEN, HIDDEN);
        // MLP block
        ln_w<true><<<ROWS / 8, 256>>>(h, ln2g + bo, ln2b + bo, xnh);
        tgemm<1><<<dim3(MLPD / 128, 25), 256, GEMM_SMEM>>>(
            xnh, wrh + 4 * MEG, wrh, wrh, fc1b + (size_t)l * MLPD, fc1b, fc1b,
            nullptr, (float*)mlph, (float*)mlph, (float*)mlph, ROWS, MLPD, HIDDEN);
        tgemm<2><<<dim3(8, 25), 256, GEMM_SMEM>>>(
            mlph, wrh + 8 * MEG, wrh, wrh, fc2b + bo, fc2b, fc2b,
            h, h, h, h, ROWS, HIDDEN, MLPD);
    }

    ln_w<false><<<ROWS / 8, 256>>>(h, lnfg, lnfb, out);
}

// round 17
// speedup vs baseline: 1.0207x; 1.0073x over previous
#include <cuda_runtime.h>
#include <cuda_fp16.h>
#include <math.h>
#include <stdint.h>

#define HIDDEN 1024
#define HEADS 16
#define HEADD 64
#define LAYERS 4
#define MLPD 4096
#define NTOK 1568
#define BATCH 2
#define ROWS (BATCH * NTOK)          // 3136
#define PATCH_K 1536                 // 3*2*16*16
#define MEG (1 << 20)

// ---------------- scratch (device globals; no allocation allowed) ----------------
__device__ float  g_h  [ROWS * HIDDEN];
__device__ __half g_qh  [ROWS * HIDDEN];
__device__ __half g_kh  [ROWS * HIDDEN];
__device__ __half g_vh  [ROWS * HIDDEN];
__device__ __half g_xnh [ROWS * HIDDEN];
__device__ __half g_aoh [ROWS * HIDDEN];
__device__ __half g_mlph[ROWS * MLPD];
__device__ __half g_colh[ROWS * PATCH_K];
__device__ __half g_wrh [50 * MEG];   // all layers' fp16 weights + patch embed

// omega_i = 10000^(-i/10), i = 0..9
__constant__ float c_OM[10] = {
    1.0f, 0.3981071705534972f, 0.15848931924611134f, 0.06309573444801933f,
    0.025118864315095794f, 0.01f, 0.003981071705534973f, 0.001584893192461113f,
    0.0006309573444801932f, 0.00025118864315095795f
};

__device__ __forceinline__ uint32_t pack2(float a, float b) {
    __half2 h = __floats2half2_rn(a, b);
    return *(uint32_t*)&h;
}

// ---------------- one-shot weight conversion to fp16 (all layers + patch) --------
// Layout (halves): layer l at l*12*MEG: q,k,v,p at +0/+MEG/+2MEG/+3MEG,
// fc1 at +4MEG, fc2 at +8MEG. Patch weights at 48*MEG.
__global__ void round_all_k(const float* __restrict__ qw, const float* __restrict__ kw,
                            const float* __restrict__ vw, const float* __restrict__ pw,
                            const float* __restrict__ f1, const float* __restrict__ f2,
                            const float* __restrict__ patw, __half* __restrict__ out) {
    const int PER_L = 3 * MEG;                 // float4 per layer
    const int TOT_L = 4 * PER_L;               // 12 MEG float4
    const int PATCH4 = HIDDEN * PATCH_K / 4;   // 393216 float4
    int i = blockIdx.x * 256 + threadIdx.x;
    if (i >= TOT_L + PATCH4) return;
    const float* src;
    size_t base;
    if (i < TOT_L) {
        int layer = i / PER_L;
        int j = i - layer * PER_L;
        int u = j >> 18;
        if (u < 4) {
            src = (u == 0) ? qw : (u == 1) ? kw : (u == 2) ? vw : pw;
            base = (size_t)layer * 262144 + (j & 262143);
        } else if (u < 8) {
            src = f1; base = (size_t)layer * MEG + (j - 4 * 262144);
        } else {
            src = f2; base = (size_t)layer * MEG + (j - 8 * 262144);
        }
    } else {
        src = patw; base = (size_t)(i - TOT_L);
    }
    float4 v = ((const float4*)src)[base];
    ((uint2*)out)[i] = make_uint2(pack2(v.x, v.y), pack2(v.z, v.w));
}

// ---------------- im2col (stores fp16) ----------------
__global__ void im2col_k(const float* __restrict__ px, __half* __restrict__ col) {
    int idx = blockIdx.x * 256 + threadIdx.x;
    if (idx >= ROWS * PATCH_K) return;
    int m = idx / PATCH_K;
    int j = idx - m * PATCH_K;
    int c  = j >> 9;
    int r  = j & 511;
    int t  = r >> 8;
    int ph = (r >> 4) & 15;
    int pw = r & 15;
    int b = m / NTOK;
    int n = m - b * NTOK;
    int d  = n / 196;
    int rr = n - d * 196;
    int hy = rr / 14;
    int wx = rr - hy * 14;
    size_t src = ((size_t)((b * 16 + d * 2 + t) * 3 + c)) * (224 * 224)
               + (size_t)(hy * 16 + ph) * 224 + (wx * 16 + pw);
    col[idx] = __float2half_rn(px[src]);
}

// ---------------- fp16 tensor-core GEMM: cp.async 3-stage + ldmatrix ----------------
__device__ __forceinline__ void mma16(float* c, uint32_t a0, uint32_t a1, uint32_t a2,
                                      uint32_t a3, uint32_t b0, uint32_t b1) {
    asm volatile(
        "mma.sync.aligned.m16n8k16.row.col.f32.f16.f16.f32 "
        "{%0,%1,%2,%3},{%4,%5,%6,%7},{%8,%9},{%0,%1,%2,%3};"
        : "+f"(c[0]), "+f"(c[1]), "+f"(c[2]), "+f"(c[3])
        : "r"(a0), "r"(a1), "r"(a2), "r"(a3), "r"(b0), "r"(b1));
}
__device__ __forceinline__ void cpa16(uint32_t dst, const void* src, int szbytes) {
    asm volatile("cp.async.cg.shared.global [%0], [%1], 16, %2;"
                 :: "r"(dst), "l"(src), "r"(szbytes) : "memory");
}
#define CP_COMMIT() asm volatile("cp.async.commit_group;" ::: "memory")

#define RSU 36                         // u32 row stride
#define TILE_U32 (128 * RSU)           // 4608 u32 per operand tile
#define STAGE_BYTES (2 * TILE_U32 * 4) // 36864
#define GEMM_SMEM (3 * STAGE_BYTES)    // 110592

template <int MODE>
__global__ __launch_bounds__(256, 2) void tgemm(
    const __half* __restrict__ A,
    const __half* __restrict__ B0, const __half* __restrict__ B1, const __half* __restrict__ B2,
    const float* __restrict__ bias0, const float* __restrict__ bias1, const float* __restrict__ bias2,
    const float* __restrict__ res, float* __restrict__ C0, float* __restrict__ C1,
    float* __restrict__ C2, int M, int N, int K)
{
    extern __shared__ uint32_t smu[];
    uint32_t smbase;
    asm("{ .reg .u64 t; cvta.to.shared.u64 t, %1; cvt.u32.u64 %0, t; }"
        : "=r"(smbase) : "l"(smu));

    int m0 = blockIdx.y * 128;
    int n0 = blockIdx.x * 128;
    const __half* B = B0;
    const float* bias = bias0;
    float* C = C0;
    int wsel = 0;
    if (MODE == 3) {
        wsel = n0 >> 10;
        if (wsel == 1) { B = B1; bias = bias1; C = C1; }
        else if (wsel == 2) { B = B2; bias = bias2; C = C2; }
        n0 &= 1023;
    }

    const int t = threadIdx.x;
    const int warp = t >> 5, lane = t & 31;
    const int wm = (warp >> 2) * 64, wn = (warp & 3) * 32;
    const int g = lane >> 2, tig = lane & 3;

    const int asub = lane >> 3;
    const uint32_t a_off =
        (uint32_t)((wm + ((asub & 1) << 3) + (lane & 7)) * (RSU * 4) + (asub >> 1) * 16);
    const int bcol = wn + (lane & 7) + ((lane >> 4) << 3);
    const uint32_t b_off =
        (uint32_t)(bcol * (RSU * 4) + ((lane >> 3) & 1) * 16);

    float acc[4][4][4];
#pragma unroll
    for (int i = 0; i < 4; i++)
#pragma unroll
        for (int j = 0; j < 4; j++)
#pragma unroll
            for (int q = 0; q < 4; q++) acc[i][j][q] = 0.f;

    const int NC = K >> 6;

    auto stage_cp = [&](int s, int k0) {
        uint32_t sb = smbase + (uint32_t)s * STAGE_BYTES;
#pragma unroll
        for (int i = 0; i < 4; i++) {
            int e = t + i * 256;
            int row = e >> 3, c = e & 7;
            uint32_t off = (uint32_t)((row * RSU + c * 4) * 4);
            int gm = m0 + row;
            const __half* srcA = A + (size_t)(gm < M ? gm : 0) * K + k0 + c * 8;
            cpa16(sb + off, srcA, gm < M ? 16 : 0);
            int gn = n0 + row;
            const __half* srcB = B + (size_t)gn * K + k0 + c * 8;
            cpa16(sb + TILE_U32 * 4 + off, srcB, 16);
        }
    };

    auto compute = [&](int s) {
        uint32_t ab = smbase + (uint32_t)s * STAGE_BYTES;
        uint32_t bb = ab + TILE_U32 * 4;
#pragma unroll
        for (int gg = 0; gg < 4; gg++) {
            uint32_t pa[4][4];
#pragma unroll
            for (int fm = 0; fm < 4; fm++) {
                uint32_t addr = ab + a_off + (uint32_t)(fm * 16 * RSU * 4 + gg * 32);
                asm volatile(
                    "ldmatrix.sync.aligned.m8n8.x4.shared.b16 {%0,%1,%2,%3}, [%4];"
                    : "=r"(pa[fm][0]), "=r"(pa[fm][1]), "=r"(pa[fm][2]), "=r"(pa[fm][3])
                    : "r"(addr));
            }
            uint32_t pb[2][4];
#pragma unroll
            for (int p = 0; p < 2; p++) {
                uint32_t addr = bb + b_off + (uint32_t)(p * 16 * RSU * 4 + gg * 32);
                asm volatile(
                    "ldmatrix.sync.aligned.m8n8.x4.shared.b16 {%0,%1,%2,%3}, [%4];"
                    : "=r"(pb[p][0]), "=r"(pb[p][1]), "=r"(pb[p][2]), "=r"(pb[p][3])
                    : "r"(addr));
            }
#pragma unroll
            for (int fm = 0; fm < 4; fm++)
#pragma unroll
                for (int fn = 0; fn < 4; fn++)
                    mma16(acc[fm][fn], pa[fm][0], pa[fm][1], pa[fm][2], pa[fm][3],
                          pb[fn >> 1][(fn & 1) * 2], pb[fn >> 1][(fn & 1) * 2 + 1]);
        }
    };

    stage_cp(0, 0);
    CP_COMMIT();
    if (NC > 1) { stage_cp(1, 64); CP_COMMIT(); }

    for (int c = 0; c < NC; c++) {
        if (c + 1 < NC) asm volatile("cp.async.wait_group 1;" ::: "memory");
        else            asm volatile("cp.async.wait_group 0;" ::: "memory");
        __syncthreads();
        if (c + 2 < NC) { stage_cp((c + 2) % 3, (c + 2) << 6); CP_COMMIT(); }
        compute(c % 3);
    }

    // epilogue
    __half* Ch = (__half*)C;
#pragma unroll
    for (int fm = 0; fm < 4; fm++) {
        int r0 = m0 + wm + fm * 16 + g;
#pragma unroll
        for (int fn = 0; fn < 4; fn++) {
            int col = n0 + wn + fn * 8 + 2 * tig;
            float b0v = bias[col], b1v = bias[col + 1];
            float om0 = 0.f, om1 = 0.f;
            int axis = 3;
            if (MODE == 3 && wsel < 2) {
                int j = (col & 63) >> 1;
                if (j < 30) {
                    axis = j / 10;
                    int i = j - axis * 10;
                    int i0 = (2 * i) % 10, i1 = (2 * i + 1) % 10;
                    om0 = c_OM[i0]; om1 = c_OM[i1];
                }
            }
#pragma unroll
            for (int hrow = 0; hrow < 2; hrow++) {
                int r = r0 + hrow * 8;
                if (r >= M) continue;
                float v0 = acc[fm][fn][hrow * 2 + 0] + b0v;
                float v1 = acc[fm][fn][hrow * 2 + 1] + b1v;
                if (MODE == 1) {
                    v0 = 0.5f * v0 * (1.f + erff(v0 * 0.70710678118654752f));
                    v1 = 0.5f * v1 * (1.f + erff(v1 * 0.70710678118654752f));
                    *(uint32_t*)&Ch[(size_t)r * N + col] = pack2(v0, v1);
                } else if (MODE == 3) {
                    if (wsel < 2 && axis < 3) {
                        int n = r % NTOK;
                        int dpos = n / 196, rem = n - dpos * 196;
                        int pos = (axis == 0) ? dpos : (axis == 1) ? (rem / 14) : (rem % 14);
                        float fp = (float)pos;
                        float s0, c0, s1, c1;
                        __sincosf(fp * om0, &s0, &c0);
                        __sincosf(fp * om1, &s1, &c1);
                        float nv0 = v0 * c0 - v1 * s0;
                        float nv1 = v1 * c1 + v0 * s1;
                        v0 = nv0; v1 = nv1;
                    }
                    if (wsel == 0) { v0 *= 0.125f; v1 *= 0.125f; }
                    *(uint32_t*)&Ch[(size_t)r * N + col] = pack2(v0, v1);
                } else {
                    if (MODE == 2) {
                        const float* rr = &res[(size_t)r * N + col];
                        v0 += rr[0]; v1 += rr[1];
                    }
                    *(float2*)&C[(size_t)r * N + col] = make_float2(v0, v1);
                }
            }
        }
    }
}

// ---------------- LayerNorm: warp-per-row, no barriers ----------------
template <bool HALF_OUT>
__global__ __launch_bounds__(256) void ln_w(
    const float* __restrict__ x, const float* __restrict__ g,
    const float* __restrict__ b, void* __restrict__ yv)
{
    int warp = threadIdx.x >> 5, lane = threadIdx.x & 31;
    int row = blockIdx.x * 8 + warp;
    const float* xr = x + (size_t)row * HIDDEN;

    float4 v[8];
    float s = 0.f;
#pragma unroll
    for (int i = 0; i < 8; i++) {
        v[i] = ((const float4*)xr)[i * 32 + lane];
        s += (v[i].x + v[i].y) + (v[i].z + v[i].w);
    }
#pragma unroll
    for (int o = 16; o > 0; o >>= 1) s += __shfl_xor_sync(~0u, s, o);
    float mu = s * (1.f / HIDDEN);

    float s2 = 0.f;
#pragma unroll
    for (int i = 0; i < 8; i++) {
        float d0 = v[i].x - mu, d1 = v[i].y - mu, d2 = v[i].z - mu, d3 = v[i].w - mu;
        s2 += (d0 * d0 + d1 * d1) + (d2 * d2 + d3 * d3);
    }
#pragma unroll
    for (int o = 16; o > 0; o >>= 1) s2 += __shfl_xor_sync(~0u, s2, o);
    float rs = rsqrtf(s2 * (1.f / HIDDEN) + 1e-6f);

#pragma unroll
    for (int i = 0; i < 8; i++) {
        int c = (i * 32 + lane) * 4;
        float4 gv = *(const float4*)&g[c];
        float4 bv = *(const float4*)&b[c];
        float o0 = (v[i].x - mu) * rs * gv.x + bv.x;
        float o1 = (v[i].y - mu) * rs * gv.y + bv.y;
        float o2 = (v[i].z - mu) * rs * gv.z + bv.z;
        float o3 = (v[i].w - mu) * rs * gv.w + bv.w;
        if (HALF_OUT) {
            *(uint2*)&((__half*)yv)[(size_t)row * HIDDEN + c] =
                make_uint2(pack2(o0, o1), pack2(o2, o3));
        } else {
            *(float4*)&((float*)yv)[(size_t)row * HIDDEN + c] =
                make_float4(o0, o1, o2, o3);
        }
    }
}

// ---------------- Flash attention: Q-tile 128, cp.async 3-stage K/V pipeline ------
#define AKST 36
#define ASTG_U32 (2 * 64 * AKST)
#define ATTN_SMEM ((3 * ASTG_U32 + 128 * AKST) * 4)   // 73728 bytes

__global__ __launch_bounds__(256, 2) void attn_h(
    const __half* __restrict__ Q, const __half* __restrict__ K,
    const __half* __restrict__ V, __half* __restrict__ O)
{
    extern __shared__ uint32_t smu[];
    uint32_t smb;
    asm("{ .reg .u64 t; cvta.to.shared.u64 t, %1; cvt.u32.u64 %0, t; }"
        : "=r"(smb) : "l"(smu));

    int b = blockIdx.y >> 4, h = blockIdx.y & 15;
    int q0 = blockIdx.x * 128;
    int tid = threadIdx.x, w = tid >> 5, lane = tid & 31;
    int g = lane >> 2, tq = lane & 3;

    const __half* Qb = Q + (size_t)b * NTOK * HIDDEN + h * HEADD;
    const __half* Kb = K + (size_t)b * NTOK * HIDDEN + h * HEADD;
    const __half* Vb = V + (size_t)b * NTOK * HIDDEN + h * HEADD;

    uint32_t qa[4][4];
    int qrow0 = q0 + w * 16 + g;
    int qrow1 = qrow0 + 8;
    bool qv0 = qrow0 < NTOK, qv1 = qrow1 < NTOK;
    const __half* qp0 = Qb + (size_t)qrow0 * HIDDEN;
    const __half* qp1 = Qb + (size_t)qrow1 * HIDDEN;
#pragma unroll
    for (int ks = 0; ks < 4; ks++) {
        int d0 = ks * 16 + 2 * tq;
        qa[ks][0] = qv0 ? *(const uint32_t*)&qp0[d0] : 0u;
        qa[ks][1] = qv1 ? *(const uint32_t*)&qp1[d0] : 0u;
        qa[ks][2] = qv0 ? *(const uint32_t*)&qp0[d0 + 8] : 0u;
        qa[ks][3] = qv1 ? *(const uint32_t*)&qp1[d0 + 8] : 0u;
    }

    float oacc[8][4];
#pragma unroll
    for (int i = 0; i < 8; i++)
#pragma unroll
        for (int j = 0; j < 4; j++) oacc[i][j] = 0.f;
    float m0 = -1e30f, m1 = -1e30f, l0 = 0.f, l1 = 0.f;

    uint32_t* pw = smu + 3 * ASTG_U32 + w * 16 * AKST;

    int vrow = (lane & 7) + ((lane >> 3) & 1) * 8;
    int vcol = (lane >> 4) * 8;
    uint32_t vaddr_base = (uint32_t)(vrow * AKST * 4 + vcol * 2);

    auto stage_kv = [&](int s, int kt) {
        int k0 = kt * 64;
        uint32_t base = smb + (uint32_t)(s * ASTG_U32 * 4);
#pragma unroll
        for (int i = 0; i < 2; i++) {
            int e = tid + i * 256;
            int r = e >> 3, c = e & 7;
            int ki = k0 + r;
            int ok = (ki < NTOK) ? 16 : 0;
            size_t ro = (size_t)(ki < NTOK ? ki : 0) * HIDDEN + c * 8;
            uint32_t off = (uint32_t)((r * AKST + c * 4) * 4);
            cpa16(base + off, Kb + ro, ok);
            cpa16(base + (uint32_t)(64 * AKST * 4) + off, Vb + ro, ok);
        }
    };

    stage_kv(0, 0);
    CP_COMMIT();
    stage_kv(1, 1);
    CP_COMMIT();

    for (int kt = 0; kt < 25; kt++) {
        if (kt < 24) asm volatile("cp.async.wait_group 1;" ::: "memory");
        else         asm volatile("cp.async.wait_group 0;" ::: "memory");
        __syncthreads();
        if (kt + 2 < 25) { stage_kv((kt + 2) % 3, kt + 2); CP_COMMIT(); }

        int s = kt % 3;
        int k0 = kt * 64;
        const uint32_t* Kst = smu + s * ASTG_U32;

        float sacc[8][4];
#pragma unroll
        for (int nf = 0; nf < 8; nf++) {
            sacc[nf][0] = 0.f; sacc[nf][1] = 0.f; sacc[nf][2] = 0.f; sacc[nf][3] = 0.f;
            const uint32_t* krow = &Kst[(nf * 8 + g) * AKST];
#pragma unroll
            for (int ks = 0; ks < 4; ks++) {
                uint32_t b0 = krow[ks * 8 + tq];
                uint32_t b1 = krow[ks * 8 + tq + 4];
                mma16(sacc[nf], qa[ks][0], qa[ks][1], qa[ks][2], qa[ks][3], b0, b1);
            }
        }

        float mx0 = -1e30f, mx1 = -1e30f;
#pragma unroll
        for (int nf = 0; nf < 8; nf++) {
            int col0 = k0 + nf * 8 + 2 * tq;
            if (col0 >= NTOK)     { sacc[nf][0] = -1e30f; sacc[nf][2] = -1e30f; }
            if (col0 + 1 >= NTOK) { sacc[nf][1] = -1e30f; sacc[nf][3] = -1e30f; }
            mx0 = fmaxf(mx0, fmaxf(sacc[nf][0], sacc[nf][1]));
            mx1 = fmaxf(mx1, fmaxf(sacc[nf][2], sacc[nf][3]));
        }
        mx0 = fmaxf(mx0, __shfl_xor_sync(~0u, mx0, 1));
        mx0 = fmaxf(mx0, __shfl_xor_sync(~0u, mx0, 2));
        mx1 = fmaxf(mx1, __shfl_xor_sync(~0u, mx1, 1));
        mx1 = fmaxf(mx1, __shfl_xor_sync(~0u, mx1, 2));
        float mn0 = fmaxf(m0, mx0), mn1 = fmaxf(m1, mx1);
        float corr0 = __expf(m0 - mn0), corr1 = __expf(m1 - mn1);
        m0 = mn0; m1 = mn1;

        float ls0 = 0.f, ls1 = 0.f;
#pragma unroll
        for (int nf = 0; nf < 8; nf++) {
            float p0 = __expf(sacc[nf][0] - mn0);
            float p1 = __expf(sacc[nf][1] - mn0);
            float p2 = __expf(sacc[nf][2] - mn1);
            float p3 = __expf(sacc[nf][3] - mn1);
            ls0 += p0 + p1; ls1 += p2 + p3;
            pw[g * AKST + nf * 4 + tq]       = pack2(p0, p1);
            pw[(g + 8) * AKST + nf * 4 + tq] = pack2(p2, p3);
        }
        ls0 += __shfl_xor_sync(~0u, ls0, 1);
        ls0 += __shfl_xor_sync(~0u, ls0, 2);
        ls1 += __shfl_xor_sync(~0u, ls1, 1);
        ls1 += __shfl_xor_sync(~0u, ls1, 2);
        l0 = l0 * corr0 + ls0;
        l1 = l1 * corr1 + ls1;
#pragma unroll
        for (int nf2 = 0; nf2 < 8; nf2++) {
            oacc[nf2][0] *= corr0; oacc[nf2][1] *= corr0;
            oacc[nf2][2] *= corr1; oacc[nf2][3] *= corr1;
        }
        __syncwarp();

        uint32_t vaddr_t = smb + (uint32_t)(s * ASTG_U32 * 4 + 64 * AKST * 4) + vaddr_base;
#pragma unroll
        for (int ks = 0; ks < 4; ks++) {
            uint32_t a0 = pw[g * AKST + ks * 8 + tq];
            uint32_t a1 = pw[(g + 8) * AKST + ks * 8 + tq];
            uint32_t a2 = pw[g * AKST + ks * 8 + tq + 4];
            uint32_t a3 = pw[(g + 8) * AKST + ks * 8 + tq + 4];
#pragma unroll
            for (int nfp = 0; nfp < 4; nfp++) {
                uint32_t addr = vaddr_t + (uint32_t)(ks * 16 * AKST * 4 + nfp * 32);
                uint32_t v0, v1, v2, v3;
                asm volatile(
                    "ldmatrix.sync.aligned.m8n8.x4.trans.shared.b16 {%0,%1,%2,%3}, [%4];"
                    : "=r"(v0), "=r"(v1), "=r"(v2), "=r"(v3) : "r"(addr));
                mma16(oacc[nfp * 2],     a0, a1, a2, a3, v0, v1);
                mma16(oacc[nfp * 2 + 1], a0, a1, a2, a3, v2, v3);
            }
        }
        __syncwarp();
    }

    float inv0 = 1.f / l0, inv1 = 1.f / l1;
    __half* Ob = O + (size_t)b * NTOK * HIDDEN + h * HEADD;
#pragma unroll
    for (int nf2 = 0; nf2 < 8; nf2++) {
        int d0 = nf2 * 8 + 2 * tq;
        if (qv0)
            *(uint32_t*)&Ob[(size_t)qrow0 * HIDDEN + d0] =
                pack2(oacc[nf2][0] * inv0, oacc[nf2][1] * inv0);
        if (qv1)
            *(uint32_t*)&Ob[(size_t)qrow1 * HIDDEN + d0] =
                pack2(oacc[nf2][2] * inv1, oacc[nf2][3] * inv1);
    }
}

// ---------------- host orchestration ----------------
extern "C" void kernel_launch(void* const* d_in, const int* in_sizes, int n_in,
                              void* d_out, int out_size) {
    (void)in_sizes; (void)n_in; (void)out_size;
    const float* px      = (const float*)d_in[0];
    const float* patch_w = (const float*)d_in[1];
    const float* patch_b = (const float*)d_in[2];
    const float* ln1g = (const float*)d_in[3];
    const float* ln1b = (const float*)d_in[4];
    const float* qw = (const float*)d_in[5];
    const float* qb = (const float*)d_in[6];
    const float* kw = (const float*)d_in[7];
    const float* kb = (const float*)d_in[8];
    const float* vw = (const float*)d_in[9];
    const float* vb = (const float*)d_in[10];
    const float* pw = (const float*)d_in[11];
    const float* pb = (const float*)d_in[12];
    const float* ln2g = (const float*)d_in[13];
    const float* ln2b = (const float*)d_in[14];
    const float* fc1w = (const float*)d_in[15];
    const float* fc1b = (const float*)d_in[16];
    const float* fc2w = (const float*)d_in[17];
    const float* fc2b = (const float*)d_in[18];
    const float* lnfg = (const float*)d_in[19];
    const float* lnfb = (const float*)d_in[20];
    float* out = (float*)d_out;

    void *ph, *pqh, *pkh, *pvh, *pxnh, *paoh, *pmlph, *pcolh, *pwrh;
    cudaGetSymbolAddress(&ph,  g_h);
    cudaGetSymbolAddress(&pqh, g_qh);
    cudaGetSymbolAddress(&pkh, g_kh);
    cudaGetSymbolAddress(&pvh, g_vh);
    cudaGetSymbolAddress(&pxnh, g_xnh);
    cudaGetSymbolAddress(&paoh, g_aoh);
    cudaGetSymbolAddress(&pmlph, g_mlph);
    cudaGetSymbolAddress(&pcolh, g_colh);
    cudaGetSymbolAddress(&pwrh, g_wrh);
    float*  h    = (float*)ph;
    __half* qh   = (__half*)pqh;
    __half* kh   = (__half*)pkh;
    __half* vh   = (__half*)pvh;
    __half* xnh  = (__half*)pxnh;
    __half* aoh  = (__half*)paoh;
    __half* mlph = (__half*)pmlph;
    __half* colh = (__half*)pcolh;
    __half* wrh  = (__half*)pwrh;

    cudaFuncSetAttribute(tgemm<0>, cudaFuncAttributeMaxDynamicSharedMemorySize, GEMM_SMEM);
    cudaFuncSetAttribute(tgemm<1>, cudaFuncAttributeMaxDynamicSharedMemorySize, GEMM_SMEM);
    cudaFuncSetAttribute(tgemm<2>, cudaFuncAttributeMaxDynamicSharedMemorySize, GEMM_SMEM);
    cudaFuncSetAttribute(tgemm<3>, cudaFuncAttributeMaxDynamicSharedMemorySize, GEMM_SMEM);
    cudaFuncSetAttribute(attn_h, cudaFuncAttributeMaxDynamicSharedMemorySize, ATTN_SMEM);

    // one-shot weight conversion (all layers + patch), then im2col + patch embed
    const int TOTAL4 = 12 * MEG + HIDDEN * PATCH_K / 4;
    round_all_k<<<(TOTAL4 + 255) / 256, 256>>>(qw, kw, vw, pw, fc1w, fc2w, patch_w, wrh);
    im2col_k<<<(ROWS * PATCH_K + 255) / 256, 256>>>(px, colh);
    __half* patw_h = wrh + (size_t)48 * MEG;
    tgemm<0><<<dim3(8, 25), 256, GEMM_SMEM>>>(
        colh, patw_h, patw_h, patw_h, patch_b, patch_b, patch_b,
        nullptr, h, h, h, ROWS, HIDDEN, PATCH_K);

    for (int l = 0; l < LAYERS; l++) {
        size_t bo = (size_t)l * HIDDEN;
        __half* wrl = wrh + (size_t)l * 12 * MEG;
        // attention block (RoPE fused into QKV epilogue)
        ln_w<true><<<ROWS / 8, 256>>>(h, ln1g + bo, ln1b + bo, xnh);
        tgemm<3><<<dim3(24, 25), 256, GEMM_SMEM>>>(
            xnh, wrl, wrl + MEG, wrl + 2 * MEG, qb + bo, kb + bo, vb + bo,
            nullptr, (float*)qh, (float*)kh, (float*)vh, ROWS, HIDDEN, HIDDEN);
        attn_h<<<dim3(13, BATCH * HEADS), 256, ATTN_SMEM>>>(qh, kh, vh, aoh);
        tgemm<2><<<dim3(8, 25), 256, GEMM_SMEM>>>(
            aoh, wrl + 3 * MEG, wrl, wrl, pb + bo, pb + bo, pb + bo,
            h, h, h, h, ROWS, HIDDEN, HIDDEN);
        // MLP block
        ln_w<true><<<ROWS / 8, 256>>>(h, ln2g + bo, ln2b + bo, xnh);
        tgemm<1><<<dim3(MLPD / 128, 25), 256, GEMM_SMEM>>>(
            xnh, wrl + 4 * MEG, wrl, wrl, fc1b + (size_t)l * MLPD, fc1b, fc1b,
            nullptr, (float*)mlph, (float*)mlph, (float*)mlph, ROWS, MLPD, HIDDEN);
        tgemm<2><<<dim3(8, 25), 256, GEMM_SMEM>>>(
            mlph, wrl + 8 * MEG, wrl, wrl, fc2b + bo, fc2b, fc2b,
            h, h, h, h, ROWS, HIDDEN, MLPD);
    }

    ln_w<false><<<ROWS / 8, 256>>>(h, lnfg, lnfb, out);
}